// round 6
// baseline (speedup 1.0000x reference)
#include <cuda_runtime.h>
#include <cuda_fp16.h>

#define NN 50000
#define D  64
#define NE 800000
#define H  128
#define NTILES 391          // 128-row tiles

typedef unsigned int u32;

// Scatter accumulator (zeroed each run; (1+eps)*x added during MLP staging).
__device__ __align__(16) float g_agg[NN * D];
__device__ int g_idx_is64;

// ---- smem layout (bytes). Padded strides -> conflict-free fragment LDS. ----
#define OFF_A1  0            // [128 rows][72 halves], k=64 used   (18432 B)
#define OFF_W1T 18432        // [128 n][72 halves],   k=64 used    (18432 B)
#define OFF_W2T 36864        // [64 n][136 halves],   k=128 used   (17408 B)
#define OFF_SB1 54272        // 128 floats
#define OFF_SB2 54784        // 64 floats
#define SMEM_BYTES 55040

// ---------------------------------------------------------------------------
__device__ __forceinline__ u32 pack_h2(float lo, float hi) {
    __half2 h = __floats2half2_rn(lo, hi);     // x=lo (low half), y=hi
    return *(u32*)&h;
}
__device__ __forceinline__ void mma_f16(float* c, const u32* a, u32 b0, u32 b1) {
    asm volatile(
        "mma.sync.aligned.m16n8k16.row.col.f32.f16.f16.f32 "
        "{%0,%1,%2,%3}, {%4,%5,%6,%7}, {%8,%9}, {%0,%1,%2,%3};"
        : "+f"(c[0]), "+f"(c[1]), "+f"(c[2]), "+f"(c[3])
        : "r"(a[0]), "r"(a[1]), "r"(a[2]), "r"(a[3]), "r"(b0), "r"(b1));
}

// ---------------------------------------------------------------------------
// Kernel 1: zero g_agg; block 0 also detects edge_index dtype (ids in [0,NN);
// an int32 buffer read as int64 packs two ids -> >= 2^32 unless hi word 0).
// ---------------------------------------------------------------------------
__global__ void zero_kernel(const void* __restrict__ ei) {
    if (blockIdx.x == 0 && threadIdx.x < 128) {
        __shared__ int bad;
        if (threadIdx.x == 0) bad = 0;
        __syncthreads();
        long long v = ((const long long*)ei)[threadIdx.x];
        if (v < 0 || v >= NN) atomicOr(&bad, 1);
        __syncthreads();
        if (threadIdx.x == 0) g_idx_is64 = !bad;
    }
    int i = blockIdx.x * blockDim.x + threadIdx.x;
    if (i < NN * D / 4)
        reinterpret_cast<float4*>(g_agg)[i] = make_float4(0.f, 0.f, 0.f, 0.f);
}

// ---------------------------------------------------------------------------
// Kernel 2: scatter-add, 16 threads/edge (contiguous 256B row),
// red.global.add.v4.f32. At the LTS throughput cap.
// ---------------------------------------------------------------------------
__global__ void scatter_kernel(const float* __restrict__ x,
                               const void* __restrict__ ei) {
    int idx = blockIdx.x * blockDim.x + threadIdx.x;
    if (idx >= NE * 16) return;
    int e = idx >> 4;
    int c = idx & 15;
    int dst_n, src_n;
    if (g_idx_is64) {
        const long long* p = (const long long*)ei;
        dst_n = (int)p[e];
        src_n = (int)p[NE + e];
    } else {
        const int* p = (const int*)ei;
        dst_n = p[e];
        src_n = p[NE + e];
    }
    float4 v = reinterpret_cast<const float4*>(x + (size_t)src_n * D)[c];
    float* dst = g_agg + (size_t)dst_n * D + c * 4;
    asm volatile("red.global.add.v4.f32 [%0], {%1, %2, %3, %4};"
                 :: "l"(dst), "f"(v.x), "f"(v.y), "f"(v.z), "f"(v.w)
                 : "memory");
}

// ---------------------------------------------------------------------------
// Kernel 3: fp16 HMMA MLP. One 128-row tile per block, 8 warps, warp w owns
// rows 16w..16w+15.
//  phase1: C1[16x128] = A[16x64] @ W1  (4 k-steps x 16 n-tiles, fp32 acc=b1)
//  epi:    relu + pack -> phase-2 A fragments ENTIRELY IN REGISTERS
//          (m16n8 C layout == m16n8k16 A layout when n1 -> k2)
//  phase2: C2[16x64]  = h1[16x128] @ W2 (8 k-steps x 8 n-tiles, acc=b2)
// ---------------------------------------------------------------------------
__global__ __launch_bounds__(256, 2)
void mlp_kernel(const float* __restrict__ x,
                const float* __restrict__ W1, const float* __restrict__ b1,
                const float* __restrict__ W2, const float* __restrict__ b2,
                const float* __restrict__ eps, float* __restrict__ out) {
    extern __shared__ char sm[];
    int tid  = threadIdx.x;
    int wid  = tid >> 5;
    int lane = tid & 31;
    int g = lane >> 2, t = lane & 3;
    int r0 = blockIdx.x * 128;
    float s = 1.0f + eps[0];

    // ---- stage W1^T : W1[k][n] -> W1T[n][k] halves, stride 72 ----
    for (int f = tid; f < 64 * H; f += 256) {
        int k = f >> 7, n = f & 127;
        *(__half*)(sm + OFF_W1T + n * 144 + k * 2) = __float2half_rn(W1[f]);
    }
    // ---- stage W2^T : W2[k][n] -> W2T[n][k] halves, stride 136 ----
    for (int f = tid; f < H * 64; f += 256) {
        int k = f >> 6, n = f & 63;
        *(__half*)(sm + OFF_W2T + n * 272 + k * 2) = __float2half_rn(W2[f]);
    }
    if (tid < 128) ((float*)(sm + OFF_SB1))[tid] = b1[tid];
    if (tid < 64)  ((float*)(sm + OFF_SB2))[tid] = b2[tid];

    // ---- stage A1: h = (1+eps)*x + agg -> fp16, [row][k] stride 72 ----
    for (int f = tid; f < 2048; f += 256) {
        int row = f >> 4, c4 = f & 15;
        int gr = r0 + row; if (gr >= NN) gr = NN - 1;
        float4 xv = ((const float4*)x)[gr * 16 + c4];
        float4 av = ((const float4*)g_agg)[gr * 16 + c4];
        u32 p0 = pack_h2(fmaf(s, xv.x, av.x), fmaf(s, xv.y, av.y));
        u32 p1 = pack_h2(fmaf(s, xv.z, av.z), fmaf(s, xv.w, av.w));
        char* dst = sm + OFF_A1 + row * 144 + c4 * 8;
        *(u32*)dst = p0;
        *(u32*)(dst + 4) = p1;
    }
    __syncthreads();

    const float* sb1f = (const float*)(sm + OFF_SB1);
    const float* sb2f = (const float*)(sm + OFF_SB2);

    // ---- phase 1 ----
    float acc[16][4];
#pragma unroll
    for (int nt = 0; nt < 16; nt++) {
        float bA = sb1f[8 * nt + 2 * t], bB = sb1f[8 * nt + 2 * t + 1];
        acc[nt][0] = bA; acc[nt][1] = bB; acc[nt][2] = bA; acc[nt][3] = bB;
    }
    {
        const char* Abase = sm + OFF_A1 + (16 * wid + g) * 144 + 4 * t;
#pragma unroll
        for (int kk = 0; kk < 4; kk++) {
            u32 aF[4];
            aF[0] = *(const u32*)(Abase + kk * 32);           // (g,   2t..)
            aF[1] = *(const u32*)(Abase + kk * 32 + 1152);    // (g+8, 2t..)
            aF[2] = *(const u32*)(Abase + kk * 32 + 16);      // (g,   2t+8..)
            aF[3] = *(const u32*)(Abase + kk * 32 + 1168);    // (g+8, 2t+8..)
#pragma unroll
            for (int nt = 0; nt < 16; nt++) {
                const char* Bb = sm + OFF_W1T + (8 * nt + g) * 144 + 4 * t + kk * 32;
                mma_f16(acc[nt], aF, *(const u32*)Bb, *(const u32*)(Bb + 16));
            }
        }
    }

    // ---- epilogue 1: relu + pack; C-frag(n-tile pair) == A-frag(k-step) ----
    u32 a2[8][4];
#pragma unroll
    for (int nt = 0; nt < 16; nt++) {
        float c0 = fmaxf(acc[nt][0], 0.f), c1 = fmaxf(acc[nt][1], 0.f);
        float c2 = fmaxf(acc[nt][2], 0.f), c3 = fmaxf(acc[nt][3], 0.f);
        int kk = nt >> 1, hf = (nt & 1) * 2;
        a2[kk][hf]     = pack_h2(c0, c1);
        a2[kk][hf + 1] = pack_h2(c2, c3);
    }

    // ---- phase 2 ----
    float acc2[8][4];
#pragma unroll
    for (int nt = 0; nt < 8; nt++) {
        float bA = sb2f[8 * nt + 2 * t], bB = sb2f[8 * nt + 2 * t + 1];
        acc2[nt][0] = bA; acc2[nt][1] = bB; acc2[nt][2] = bA; acc2[nt][3] = bB;
    }
#pragma unroll
    for (int kk = 0; kk < 8; kk++) {
#pragma unroll
        for (int nt = 0; nt < 8; nt++) {
            const char* Bb = sm + OFF_W2T + (8 * nt + g) * 272 + 4 * t + kk * 32;
            mma_f16(acc2[nt], a2[kk], *(const u32*)Bb, *(const u32*)(Bb + 16));
        }
    }

    // ---- store (rows 16w+g and 16w+g+8, cols 8nt+2t) ----
    int row0 = r0 + 16 * wid + g;
#pragma unroll
    for (int nt = 0; nt < 8; nt++) {
        int col = 8 * nt + 2 * t;
        if (row0 < NN) {
            float2 v = { acc2[nt][0], acc2[nt][1] };
            *(float2*)(out + (size_t)row0 * D + col) = v;
        }
        if (row0 + 8 < NN) {
            float2 v = { acc2[nt][2], acc2[nt][3] };
            *(float2*)(out + (size_t)(row0 + 8) * D + col) = v;
        }
    }
}

// ---------------------------------------------------------------------------
extern "C" void kernel_launch(void* const* d_in, const int* in_sizes, int n_in,
                              void* d_out, int out_size) {
    const float* x   = (const float*)d_in[0];
    const void*  ei  = d_in[1];
    const float* W1  = (const float*)d_in[2];
    const float* b1  = (const float*)d_in[3];
    const float* W2  = (const float*)d_in[4];
    const float* b2  = (const float*)d_in[5];
    const float* eps = (const float*)d_in[6];
    float* out = (float*)d_out;

    zero_kernel<<<(NN * D / 4 + 255) / 256, 256>>>(ei);
    scatter_kernel<<<(NE * 16 + 255) / 256, 256>>>(x, ei);

    cudaFuncSetAttribute(mlp_kernel,
                         cudaFuncAttributeMaxDynamicSharedMemorySize, SMEM_BYTES);
    mlp_kernel<<<NTILES, 256, SMEM_BYTES>>>(x, W1, b1, W2, b2, eps, out);
}

// round 7
// speedup vs baseline: 1.5059x; 1.5059x over previous
#include <cuda_runtime.h>
#include <cuda_fp16.h>

#define NN 50000
#define D  64
#define NE 800000
#define H  128
#define NTILES 391          // 128-row tiles

typedef unsigned int u32;

// Scatter accumulator (zeroed each run; (1+eps)*x added during MLP staging).
__device__ __align__(16) float g_agg[NN * D];
__device__ int g_idx_is64;

// ---- smem layout (bytes). Padded strides -> conflict-free fragment LDS. ----
#define OFF_A1  0            // [128 rows][72 halves], k=64 used   (18432 B)
#define OFF_W1T 18432        // [128 n][72 halves],   k=64 used    (18432 B)
#define OFF_W2T 36864        // [64 n][136 halves],   k=128 used   (17408 B)
#define OFF_SB1 54272        // 128 floats
#define OFF_SB2 54784        // 64 floats
#define SMEM_BYTES 55040

// ---------------------------------------------------------------------------
__device__ __forceinline__ u32 pack_h2(float lo, float hi) {
    __half2 h = __floats2half2_rn(lo, hi);     // x=lo (low half), y=hi
    return *(u32*)&h;
}
__device__ __forceinline__ void mma_f16(float* c, const u32* a, u32 b0, u32 b1) {
    asm volatile(
        "mma.sync.aligned.m16n8k16.row.col.f32.f16.f16.f32 "
        "{%0,%1,%2,%3}, {%4,%5,%6,%7}, {%8,%9}, {%0,%1,%2,%3};"
        : "+f"(c[0]), "+f"(c[1]), "+f"(c[2]), "+f"(c[3])
        : "r"(a[0]), "r"(a[1]), "r"(a[2]), "r"(a[3]), "r"(b0), "r"(b1));
}

// ---------------------------------------------------------------------------
// Kernel 1: zero g_agg; block 0 also detects edge_index dtype (ids in [0,NN);
// an int32 buffer read as int64 packs two ids -> >= 2^32 unless hi word 0).
// ---------------------------------------------------------------------------
__global__ void zero_kernel(const void* __restrict__ ei) {
    if (blockIdx.x == 0 && threadIdx.x < 128) {
        __shared__ int bad;
        if (threadIdx.x == 0) bad = 0;
        __syncthreads();
        long long v = ((const long long*)ei)[threadIdx.x];
        if (v < 0 || v >= NN) atomicOr(&bad, 1);
        __syncthreads();
        if (threadIdx.x == 0) g_idx_is64 = !bad;
    }
    int i = blockIdx.x * blockDim.x + threadIdx.x;
    if (i < NN * D / 4)
        reinterpret_cast<float4*>(g_agg)[i] = make_float4(0.f, 0.f, 0.f, 0.f);
}

// ---------------------------------------------------------------------------
// Kernel 2: scatter-add, 16 threads/edge (contiguous 256B row),
// red.global.add.v4.f32. At the LTS throughput cap.
// ---------------------------------------------------------------------------
__global__ void scatter_kernel(const float* __restrict__ x,
                               const void* __restrict__ ei) {
    int idx = blockIdx.x * blockDim.x + threadIdx.x;
    if (idx >= NE * 16) return;
    int e = idx >> 4;
    int c = idx & 15;
    int dst_n, src_n;
    if (g_idx_is64) {
        const long long* p = (const long long*)ei;
        dst_n = (int)p[e];
        src_n = (int)p[NE + e];
    } else {
        const int* p = (const int*)ei;
        dst_n = p[e];
        src_n = p[NE + e];
    }
    float4 v = reinterpret_cast<const float4*>(x + (size_t)src_n * D)[c];
    float* dst = g_agg + (size_t)dst_n * D + c * 4;
    asm volatile("red.global.add.v4.f32 [%0], {%1, %2, %3, %4};"
                 :: "l"(dst), "f"(v.x), "f"(v.y), "f"(v.z), "f"(v.w)
                 : "memory");
}

// ---------------------------------------------------------------------------
// Kernel 3: fp16 HMMA MLP, spill-free. One 128-row tile per block, 8 warps,
// warp w owns rows 16w..16w+15.
//  phase1 (two n-halves to bound register pressure):
//    accH[8][4] = A[16x64] @ W1[:, half]  -> relu+pack -> a2[kk] fragments
//    (m16n8 C layout == m16n8k16 A layout when n1 -> k2: NO smem round-trip)
//  phase2: C2[16x64] = h1[16x128] @ W2 (8 k-steps x 8 n-tiles, fp32 acc=b2)
// Peak live accumulator regs ~90 -> fits 128-reg budget at 2 blocks/SM.
// ---------------------------------------------------------------------------
__global__ __launch_bounds__(256, 2)
void mlp_kernel(const float* __restrict__ x,
                const float* __restrict__ W1, const float* __restrict__ b1,
                const float* __restrict__ W2, const float* __restrict__ b2,
                const float* __restrict__ eps, float* __restrict__ out) {
    extern __shared__ char sm[];
    int tid  = threadIdx.x;
    int wid  = tid >> 5;
    int lane = tid & 31;
    int g = lane >> 2, t = lane & 3;
    int r0 = blockIdx.x * 128;
    float s = 1.0f + eps[0];

    // ---- stage W1^T : W1[k][n] -> W1T[n][k] halves, stride 72 ----
    for (int f = tid; f < 64 * H; f += 256) {
        int k = f >> 7, n = f & 127;
        *(__half*)(sm + OFF_W1T + n * 144 + k * 2) = __float2half_rn(W1[f]);
    }
    // ---- stage W2^T : W2[k][n] -> W2T[n][k] halves, stride 136 ----
    for (int f = tid; f < H * 64; f += 256) {
        int k = f >> 6, n = f & 63;
        *(__half*)(sm + OFF_W2T + n * 272 + k * 2) = __float2half_rn(W2[f]);
    }
    if (tid < 128) ((float*)(sm + OFF_SB1))[tid] = b1[tid];
    if (tid < 64)  ((float*)(sm + OFF_SB2))[tid] = b2[tid];

    // ---- stage A1: h = (1+eps)*x + agg -> fp16, [row][k] stride 72 ----
    for (int f = tid; f < 2048; f += 256) {
        int row = f >> 4, c4 = f & 15;
        int gr = r0 + row; if (gr >= NN) gr = NN - 1;
        float4 xv = ((const float4*)x)[gr * 16 + c4];
        float4 av = ((const float4*)g_agg)[gr * 16 + c4];
        u32 p0 = pack_h2(fmaf(s, xv.x, av.x), fmaf(s, xv.y, av.y));
        u32 p1 = pack_h2(fmaf(s, xv.z, av.z), fmaf(s, xv.w, av.w));
        char* dst = sm + OFF_A1 + row * 144 + c4 * 8;
        *(u32*)dst = p0;
        *(u32*)(dst + 4) = p1;
    }
    __syncthreads();

    const float* sb1f = (const float*)(sm + OFF_SB1);
    const float* sb2f = (const float*)(sm + OFF_SB2);
    const char* Abase = sm + OFF_A1 + (16 * wid + g) * 144 + 4 * t;

    // ---- phase 1 in two n-halves; phase-2 A fragments built in registers ----
    u32 a2[8][4];
#pragma unroll
    for (int half = 0; half < 2; half++) {
        float acc[8][4];
#pragma unroll
        for (int nt = 0; nt < 8; nt++) {
            int n0 = 64 * half + 8 * nt;
            float bA = sb1f[n0 + 2 * t], bB = sb1f[n0 + 2 * t + 1];
            acc[nt][0] = bA; acc[nt][1] = bB; acc[nt][2] = bA; acc[nt][3] = bB;
        }
#pragma unroll
        for (int kk = 0; kk < 4; kk++) {
            u32 aF[4];
            aF[0] = *(const u32*)(Abase + kk * 32);           // (g,   2t..)
            aF[1] = *(const u32*)(Abase + kk * 32 + 1152);    // (g+8, 2t..)
            aF[2] = *(const u32*)(Abase + kk * 32 + 16);      // (g,   2t+8..)
            aF[3] = *(const u32*)(Abase + kk * 32 + 1168);    // (g+8, 2t+8..)
#pragma unroll
            for (int nt = 0; nt < 8; nt++) {
                const char* Bb = sm + OFF_W1T + (64 * half + 8 * nt + g) * 144
                               + 4 * t + kk * 32;
                mma_f16(acc[nt], aF, *(const u32*)Bb, *(const u32*)(Bb + 16));
            }
        }
        // relu + pack: n-tile pair (2nt,2nt+1) -> one k-step fragment
#pragma unroll
        for (int nt = 0; nt < 8; nt++) {
            float c0 = fmaxf(acc[nt][0], 0.f), c1 = fmaxf(acc[nt][1], 0.f);
            float c2 = fmaxf(acc[nt][2], 0.f), c3 = fmaxf(acc[nt][3], 0.f);
            int kk = 4 * half + (nt >> 1), hf = (nt & 1) * 2;
            a2[kk][hf]     = pack_h2(c0, c1);
            a2[kk][hf + 1] = pack_h2(c2, c3);
        }
    }

    // ---- phase 2 ----
    float acc2[8][4];
#pragma unroll
    for (int nt = 0; nt < 8; nt++) {
        float bA = sb2f[8 * nt + 2 * t], bB = sb2f[8 * nt + 2 * t + 1];
        acc2[nt][0] = bA; acc2[nt][1] = bB; acc2[nt][2] = bA; acc2[nt][3] = bB;
    }
#pragma unroll
    for (int kk = 0; kk < 8; kk++) {
#pragma unroll
        for (int nt = 0; nt < 8; nt++) {
            const char* Bb = sm + OFF_W2T + (8 * nt + g) * 272 + 4 * t + kk * 32;
            mma_f16(acc2[nt], a2[kk], *(const u32*)Bb, *(const u32*)(Bb + 16));
        }
    }

    // ---- store (rows 16w+g and 16w+g+8, cols 8nt+2t) ----
    int row0 = r0 + 16 * wid + g;
#pragma unroll
    for (int nt = 0; nt < 8; nt++) {
        int col = 8 * nt + 2 * t;
        if (row0 < NN) {
            float2 v = { acc2[nt][0], acc2[nt][1] };
            *(float2*)(out + (size_t)row0 * D + col) = v;
        }
        if (row0 + 8 < NN) {
            float2 v = { acc2[nt][2], acc2[nt][3] };
            *(float2*)(out + (size_t)(row0 + 8) * D + col) = v;
        }
    }
}

// ---------------------------------------------------------------------------
extern "C" void kernel_launch(void* const* d_in, const int* in_sizes, int n_in,
                              void* d_out, int out_size) {
    const float* x   = (const float*)d_in[0];
    const void*  ei  = d_in[1];
    const float* W1  = (const float*)d_in[2];
    const float* b1  = (const float*)d_in[3];
    const float* W2  = (const float*)d_in[4];
    const float* b2  = (const float*)d_in[5];
    const float* eps = (const float*)d_in[6];
    float* out = (float*)d_out;

    zero_kernel<<<(NN * D / 4 + 255) / 256, 256>>>(ei);
    scatter_kernel<<<(NE * 16 + 255) / 256, 256>>>(x, ei);

    cudaFuncSetAttribute(mlp_kernel,
                         cudaFuncAttributeMaxDynamicSharedMemorySize, SMEM_BYTES);
    mlp_kernel<<<NTILES, 256, SMEM_BYTES>>>(x, W1, b1, W2, b2, eps, out);
}